// round 7
// baseline (speedup 1.0000x reference)
#include <cuda_runtime.h>
#include <math.h>

#define B 32
#define T 128
#define BT 4096
#define E 1024
#define H 1024
#define G 4096
#define V 32000
#define NBLK 128

typedef unsigned long long ull;

// ---------------- packed f32x2 helpers ----------------
__device__ __forceinline__ ull fma2(ull a, ull b, ull c) {
    ull d;
    asm("fma.rn.f32x2 %0, %1, %2, %3;" : "=l"(d) : "l"(a), "l"(b), "l"(c));
    return d;
}
__device__ __forceinline__ ull splat2(float x) {
    ull d;
    asm("mov.b64 %0, {%1, %1};" : "=l"(d) : "f"(x));
    return d;
}
__device__ __forceinline__ void unpack2(ull v, float& lo, float& hi) {
    asm("mov.b64 {%0, %1}, %2;" : "=f"(lo), "=f"(hi) : "l"(v));
}

// ---------------- cp.async helpers ----------------
__device__ __forceinline__ void cp_async16(void* smem_ptr, const void* gptr) {
    unsigned s = (unsigned)__cvta_generic_to_shared(smem_ptr);
    asm volatile("cp.async.cg.shared.global [%0], [%1], 16;\n" :: "r"(s), "l"(gptr));
}
__device__ __forceinline__ void cp_async_commit() {
    asm volatile("cp.async.commit_group;\n");
}
__device__ __forceinline__ void cp_async_wait_all() {
    asm volatile("cp.async.wait_group 0;\n" ::: "memory");
}

// ---------------- acquire/release for grid barrier ----------------
__device__ __forceinline__ unsigned ld_acq(unsigned* p) {
    unsigned v;
    asm volatile("ld.acquire.gpu.u32 %0, [%1];" : "=r"(v) : "l"(p) : "memory");
    return v;
}
__device__ __forceinline__ void st_rel(unsigned* p, unsigned v) {
    asm volatile("st.release.gpu.u32 [%0], %1;" :: "l"(p), "r"(v) : "memory");
}

// ---------------- device scratch ----------------
__device__ __align__(16) float g_xemb[BT * E];
__device__ __align__(16) float g_gx[BT * G];
__device__ __align__(16) float g_hseq0[BT * H];
__device__ __align__(16) float g_hseq1[BT * H];
__device__ __align__(16) float g_h0[B * H];
__device__ __align__(16) float g_h1[B * H];
__device__ __align__(16) float g_c[B * H];
__device__ unsigned g_sync_count = 0;
__device__ unsigned g_sync_gen = 0;

// ---------------- embedding gather ----------------
__global__ void embed_kernel(const int* __restrict__ idx, const float* __restrict__ emb) {
    int row = blockIdx.x;
    int tok = idx[row];
    const float4* src = (const float4*)(emb + (size_t)tok * E);
    float4* dst = (float4*)(g_xemb + (size_t)row * E);
    dst[threadIdx.x] = src[threadIdx.x];
}

// ---------------- double-buffered FFMA2 SGEMM + bias ----------------
__global__ __launch_bounds__(256, 2) void sgemm_bias2(
    const float* __restrict__ A, const float* __restrict__ Bm,
    const float* __restrict__ bias, float* __restrict__ C,
    int M, int N, int K)
{
    __shared__ float As[2][8][128];
    __shared__ float Bs[2][8][128];
    int tid = threadIdx.x;
    int bx = blockIdx.x, by = blockIdx.y;
    int tx = tid & 15, ty = tid >> 4;

    const float* Ab = A + (size_t)by * 128 * K;
    const float* Bb = Bm + (size_t)bx * 128;

    int arow = tid >> 1, acol = (tid & 1) * 4;
    int brow = tid >> 5, bcol = (tid & 31) * 4;

    ull acc[8][4];
#pragma unroll
    for (int i = 0; i < 8; i++)
#pragma unroll
        for (int p = 0; p < 4; p++) acc[i][p] = 0ull;

    {
        float4 av = *(const float4*)(Ab + (size_t)arow * K + acol);
        float4 bv = *(const float4*)(Bb + (size_t)brow * N + bcol);
        As[0][acol + 0][arow] = av.x;
        As[0][acol + 1][arow] = av.y;
        As[0][acol + 2][arow] = av.z;
        As[0][acol + 3][arow] = av.w;
        *(float4*)&Bs[0][brow][bcol] = bv;
    }
    __syncthreads();

    int nk = K >> 3;
    for (int kt = 0; kt < nk; kt++) {
        int cur = kt & 1;
        float4 av, bv;
        bool more = (kt + 1 < nk);
        if (more) {
            av = *(const float4*)(Ab + (size_t)arow * K + (kt + 1) * 8 + acol);
            bv = *(const float4*)(Bb + (size_t)((kt + 1) * 8 + brow) * N + bcol);
        }
#pragma unroll
        for (int k = 0; k < 8; k++) {
            float ar[8];
            *(float4*)&ar[0] = *(const float4*)&As[cur][k][ty * 8];
            *(float4*)&ar[4] = *(const float4*)&As[cur][k][ty * 8 + 4];
            ull b2[4];
            const ull* bp = (const ull*)&Bs[cur][k][tx * 8];
            b2[0] = bp[0]; b2[1] = bp[1]; b2[2] = bp[2]; b2[3] = bp[3];
            ull a2[8];
#pragma unroll
            for (int i = 0; i < 8; i++) a2[i] = splat2(ar[i]);
#pragma unroll
            for (int i = 0; i < 8; i++)
#pragma unroll
                for (int p = 0; p < 4; p++)
                    acc[i][p] = fma2(a2[i], b2[p], acc[i][p]);
        }
        if (more) {
            int alt = cur ^ 1;
            As[alt][acol + 0][arow] = av.x;
            As[alt][acol + 1][arow] = av.y;
            As[alt][acol + 2][arow] = av.z;
            As[alt][acol + 3][arow] = av.w;
            *(float4*)&Bs[alt][brow][bcol] = bv;
        }
        __syncthreads();
    }

#pragma unroll
    for (int i = 0; i < 8; i++) {
        int row = by * 128 + ty * 8 + i;
        int col = bx * 128 + tx * 8;
        float* Cp = C + (size_t)row * N + col;
        const float* bp = bias + col;
        float c0, c1, c2, c3, c4, c5, c6, c7;
        unpack2(acc[i][0], c0, c1);
        unpack2(acc[i][1], c2, c3);
        unpack2(acc[i][2], c4, c5);
        unpack2(acc[i][3], c6, c7);
        float4 o0, o1;
        o0.x = c0 + bp[0]; o0.y = c1 + bp[1];
        o0.z = c2 + bp[2]; o0.w = c3 + bp[3];
        o1.x = c4 + bp[4]; o1.y = c5 + bp[5];
        o1.z = c6 + bp[6]; o1.w = c7 + bp[7];
        *(float4*)Cp = o0;
        *(float4*)(Cp + 4) = o1;
    }
}

// ---------------- persistent LSTM layer kernel ----------------
// 128 blocks (one per 8 hidden units), resident for all 128 timesteps.
// Weights (block's 32 gate-columns x 1024 k = 128KB) live in smem the whole
// kernel. Per step: stream h (32x1024) from L2 in 8 double-buffered chunks,
// FFMA2 microtile compute, split-k reduce via smem, fused cell update,
// software grid barrier.
//
// smem: wsm[1024][32] (128KB) | hb[2][128][36] (36KB) | red[8][32][32] (32KB)
#define WSM_F (1024 * 32)
#define HBUF_F (128 * 36)
#define RED_F (8 * 32 * 32)
#define LSTM_SMEM ((WSM_F + 2 * HBUF_F + RED_F) * 4)

__device__ __forceinline__ void grid_barrier(unsigned gen) {
    __threadfence();
    __syncthreads();
    if (threadIdx.x == 0) {
        if (atomicAdd(&g_sync_count, 1u) == NBLK - 1) {
            g_sync_count = 0;
            st_rel(&g_sync_gen, gen);
        } else {
            while (ld_acq(&g_sync_gen) != gen) { }
        }
    }
    __syncthreads();
}

__global__ __launch_bounds__(256, 1) void lstm_persist(
    const float* __restrict__ gx,     // [BT][G]
    const float* __restrict__ Wh,     // [H][G] recurrent weights
    float* __restrict__ h0g,          // [B][H] ping
    float* __restrict__ h1g,          // [B][H] pong
    float* __restrict__ c_st,         // [B][H]
    float* __restrict__ hseq)         // [BT][H]
{
    extern __shared__ float smf[];
    float* wsm = smf;                       // [k][32]: k*32 + g*8 + jj
    float* hb  = smf + WSM_F;               // [2][128][36]
    float* red = smf + WSM_F + 2 * HBUF_F;  // [s][elem][tile]

    int tid = threadIdx.x;
    int j0 = blockIdx.x * 8;

    unsigned base = 0;
    if (tid == 0) base = ld_acq(&g_sync_gen);

    // ---- load this block's weight slice into smem (once) ----
#pragma unroll
    for (int l = 0; l < 32; l++) {
        int f = tid + l * 256;
        int k = f >> 3, g = (f >> 1) & 3, hf = f & 1;
        cp_async16(&wsm[k * 32 + g * 8 + hf * 4],
                   Wh + (size_t)k * G + g * H + j0 + hf * 4);
    }
    cp_async_commit();

    // ---- zero own columns of h0 and c ----
    {
        int b = tid >> 3, jj = tid & 7;
        h0g[b * H + j0 + jj] = 0.f;
        c_st[b * H + j0 + jj] = 0.f;
    }
    cp_async_wait_all();
    grid_barrier(base + 1);

    // compute-thread mapping: warp s = k-slice, lane: bg = lane>>2, g = lane&3
    int s = tid >> 5;
    int lane = tid & 31;
    int bg = lane >> 2;
    int g = lane & 3;
    // cell-update mapping
    int eu = tid >> 3, bgu = tid & 7;
    int iu = eu >> 3, jju = eu & 7;
    int bu = bgu * 4 + iu;
    int jgu = j0 + jju;

    for (int t = 0; t < T; t++) {
        const float* hin = (t & 1) ? h1g : h0g;
        float* hout = (t & 1) ? h0g : h1g;
        const float4* h4 = (const float4*)hin;

        // stage chunk 0
        {
            float4 hreg[4];
#pragma unroll
            for (int l = 0; l < 4; l++) {
                int q = tid + l * 256;
                hreg[l] = h4[(q >> 5) * 256 + (q & 31)];
            }
#pragma unroll
            for (int l = 0; l < 4; l++) {
                int q = tid + l * 256;
                int b = q >> 5, kl = (q & 31) * 4;
                hb[(kl + 0) * 36 + b] = hreg[l].x;
                hb[(kl + 1) * 36 + b] = hreg[l].y;
                hb[(kl + 2) * 36 + b] = hreg[l].z;
                hb[(kl + 3) * 36 + b] = hreg[l].w;
            }
        }
        __syncthreads();

        ull acc[4][4];
#pragma unroll
        for (int i = 0; i < 4; i++)
#pragma unroll
            for (int p = 0; p < 4; p++) acc[i][p] = 0ull;

        for (int c = 0; c < 8; c++) {
            int d = c & 1;
            float4 hreg[4];
            bool more = (c < 7);
            if (more) {
#pragma unroll
                for (int l = 0; l < 4; l++) {
                    int q = tid + l * 256;
                    hreg[l] = h4[(q >> 5) * 256 + (c + 1) * 32 + (q & 31)];
                }
            }

            const float* hs = hb + d * HBUF_F + s * 36 + bg * 4;
            const float* wp = wsm + (c * 128 + s) * 32 + g * 8;
#pragma unroll 8
            for (int kk = 0; kk < 16; kk++) {
                float4 hv = *(const float4*)&hs[kk * (8 * 36)];
                ull w2[4];
                const ull* wq = (const ull*)&wp[kk * 256];
                w2[0] = wq[0]; w2[1] = wq[1]; w2[2] = wq[2]; w2[3] = wq[3];
                ull a0 = splat2(hv.x), a1 = splat2(hv.y);
                ull a2v = splat2(hv.z), a3 = splat2(hv.w);
#pragma unroll
                for (int p = 0; p < 4; p++) {
                    acc[0][p] = fma2(a0, w2[p], acc[0][p]);
                    acc[1][p] = fma2(a1, w2[p], acc[1][p]);
                    acc[2][p] = fma2(a2v, w2[p], acc[2][p]);
                    acc[3][p] = fma2(a3, w2[p], acc[3][p]);
                }
            }

            if (more) {
                float* hn = hb + (d ^ 1) * HBUF_F;
#pragma unroll
                for (int l = 0; l < 4; l++) {
                    int q = tid + l * 256;
                    int b = q >> 5, kl = (q & 31) * 4;
                    hn[(kl + 0) * 36 + b] = hreg[l].x;
                    hn[(kl + 1) * 36 + b] = hreg[l].y;
                    hn[(kl + 2) * 36 + b] = hreg[l].z;
                    hn[(kl + 3) * 36 + b] = hreg[l].w;
                }
            }
            __syncthreads();
        }

        // split-k reduction: red[s][elem][tile], tile = lane = bg*4+g
#pragma unroll
        for (int i = 0; i < 4; i++)
#pragma unroll
            for (int p = 0; p < 4; p++) {
                float lo, hi;
                unpack2(acc[i][p], lo, hi);
                red[s * 1024 + (i * 8 + 2 * p) * 32 + lane] = lo;
                red[s * 1024 + (i * 8 + 2 * p + 1) * 32 + lane] = hi;
            }
        __syncthreads();

        // fused cell update: thread = (bgu, eu)
        {
            float4 gs = make_float4(0.f, 0.f, 0.f, 0.f);
#pragma unroll
            for (int ss = 0; ss < 8; ss++) {
                float4 v = *(const float4*)&red[ss * 1024 + eu * 32 + bgu * 4];
                gs.x += v.x; gs.y += v.y; gs.z += v.z; gs.w += v.w;
            }
            const float* gxr = gx + (size_t)(bu * T + t) * G;
            float vi = gs.x + gxr[0 * H + jgu];
            float vj = gs.y + gxr[1 * H + jgu];
            float vf = gs.z + gxr[2 * H + jgu];
            float vo = gs.w + gxr[3 * H + jgu];
            float cold = c_st[bu * H + jgu];
            float si = 1.f / (1.f + expf(-vi));
            float sf = 1.f / (1.f + expf(-(vf + 1.f)));
            float so = 1.f / (1.f + expf(-vo));
            float cnew = sf * cold + si * tanhf(vj);
            float hnew = so * tanhf(cnew);
            c_st[bu * H + jgu] = cnew;
            hout[bu * H + jgu] = hnew;
            hseq[(size_t)(bu * T + t) * H + jgu] = hnew;
        }

        grid_barrier(base + 2 + t);
    }
}

// ---------------- launcher ----------------
extern "C" void kernel_launch(void* const* d_in, const int* in_sizes, int n_in,
                              void* d_out, int out_size)
{
    const int*   input_seq = (const int*)d_in[0];
    const float* emb = (const float*)d_in[1];
    const float* W0  = (const float*)d_in[2];
    const float* b0  = (const float*)d_in[3];
    const float* W1  = (const float*)d_in[4];
    const float* b1  = (const float*)d_in[5];
    const float* Wd  = (const float*)d_in[6];
    const float* bd  = (const float*)d_in[7];
    float* out = (float*)d_out;
    (void)in_sizes; (void)n_in; (void)out_size;

    float *xemb, *gx, *hs0, *hs1, *h0, *h1, *cbuf;
    cudaGetSymbolAddress((void**)&xemb, g_xemb);
    cudaGetSymbolAddress((void**)&gx,   g_gx);
    cudaGetSymbolAddress((void**)&hs0,  g_hseq0);
    cudaGetSymbolAddress((void**)&hs1,  g_hseq1);
    cudaGetSymbolAddress((void**)&h0,   g_h0);
    cudaGetSymbolAddress((void**)&h1,   g_h1);
    cudaGetSymbolAddress((void**)&cbuf, g_c);

    cudaFuncSetAttribute(lstm_persist, cudaFuncAttributeMaxDynamicSharedMemorySize, LSTM_SMEM);

    // 1) embedding
    embed_kernel<<<BT, 256>>>(input_seq, emb);

    // 2) layer-0 input-path gates
    dim3 gGX(G / 128, BT / 128);
    sgemm_bias2<<<gGX, 256>>>(xemb, W0, b0, gx, BT, G, E);

    // 3) layer-0 recurrence (persistent)
    lstm_persist<<<NBLK, 256, LSTM_SMEM>>>(gx, W0 + (size_t)E * G, h0, h1, cbuf, hs0);

    // 4) layer-1 input-path gates
    sgemm_bias2<<<gGX, 256>>>(hs0, W1, b1, gx, BT, G, H);

    // 5) layer-1 recurrence (persistent)
    lstm_persist<<<NBLK, 256, LSTM_SMEM>>>(gx, W1 + (size_t)H * G, h0, h1, cbuf, hs1);

    // 6) dense projection
    dim3 gOUT(V / 128, BT / 128);
    sgemm_bias2<<<gOUT, 256>>>(hs1, Wd, bd, out, BT, V, H);
}

// round 9
// speedup vs baseline: 2.0979x; 2.0979x over previous
#include <cuda_runtime.h>
#include <cuda_bf16.h>
#include <math.h>

#define B 32
#define T 128
#define BT 4096
#define E 1024
#define H 1024
#define G 4096
#define V 32000

typedef unsigned long long ull;

// ---------------- packed f32x2 helpers (sm_103 FFMA2 path) ----------------
__device__ __forceinline__ ull fma2(ull a, ull b, ull c) {
    ull d;
    asm("fma.rn.f32x2 %0, %1, %2, %3;" : "=l"(d) : "l"(a), "l"(b), "l"(c));
    return d;
}
__device__ __forceinline__ ull splat2(float x) {
    ull d;
    asm("mov.b64 %0, {%1, %1};" : "=l"(d) : "f"(x));
    return d;
}
__device__ __forceinline__ void unpack2(ull v, float& lo, float& hi) {
    asm("mov.b64 {%0, %1}, %2;" : "=f"(lo), "=f"(hi) : "l"(v));
}

// ---------------- cp.async helpers ----------------
__device__ __forceinline__ void cp_async16(void* smem_ptr, const void* gptr) {
    unsigned s = (unsigned)__cvta_generic_to_shared(smem_ptr);
    asm volatile("cp.async.cg.shared.global [%0], [%1], 16;\n" :: "r"(s), "l"(gptr));
}
__device__ __forceinline__ void cp_async16_s(unsigned dst, const void* gptr) {
    asm volatile("cp.async.cg.shared.global [%0], [%1], 16;\n" :: "r"(dst), "l"(gptr));
}
__device__ __forceinline__ void cp_async_commit() {
    asm volatile("cp.async.commit_group;\n");
}
__device__ __forceinline__ void cp_async_wait_all() {
    asm volatile("cp.async.wait_group 0;\n" ::: "memory");
}

// ---------------- mma.sync / ldmatrix helpers (plain sm_103 OK) ----------------
__device__ __forceinline__ void ldm4(unsigned* r, unsigned addr) {
    asm volatile("ldmatrix.sync.aligned.m8n8.x4.shared.b16 {%0,%1,%2,%3}, [%4];"
                 : "=r"(r[0]), "=r"(r[1]), "=r"(r[2]), "=r"(r[3]) : "r"(addr));
}
__device__ __forceinline__ void mma_bf16(float* c, const unsigned* a, unsigned b0, unsigned b1) {
    asm volatile(
        "mma.sync.aligned.m16n8k16.row.col.f32.bf16.bf16.f32 "
        "{%0,%1,%2,%3}, {%4,%5,%6,%7}, {%8,%9}, {%0,%1,%2,%3};"
        : "+f"(c[0]), "+f"(c[1]), "+f"(c[2]), "+f"(c[3])
        : "r"(a[0]), "r"(a[1]), "r"(a[2]), "r"(a[3]), "r"(b0), "r"(b1));
}
__device__ __forceinline__ unsigned swz(unsigned off) {
    return off ^ ((off >> 3) & 0x70);
}

// ---------------- device scratch ----------------
__device__ __align__(16) float g_xemb[BT * E];
__device__ __align__(16) float g_gx[BT * G];
__device__ __align__(16) float g_hseq0[BT * H];
__device__ __align__(16) float g_hseq1[BT * H];
__device__ __align__(16) float g_h0[B * H];
__device__ __align__(16) float g_h1[B * H];
__device__ __align__(16) float g_c[B * H];
__device__ __align__(16) __nv_bfloat16 g_ahi[BT * H];
__device__ __align__(16) __nv_bfloat16 g_alo[BT * H];
__device__ __align__(16) __nv_bfloat16 g_bhi[(size_t)V * H];
__device__ __align__(16) __nv_bfloat16 g_blo[(size_t)V * H];

// ---------------- embedding gather ----------------
__global__ void embed_kernel(const int* __restrict__ idx, const float* __restrict__ emb) {
    int row = blockIdx.x;
    int tok = idx[row];
    const float4* src = (const float4*)(emb + (size_t)tok * E);
    float4* dst = (float4*)(g_xemb + (size_t)row * E);
    dst[threadIdx.x] = src[threadIdx.x];
}

__global__ void zero_state_kernel() {
    int i = blockIdx.x * blockDim.x + threadIdx.x;
    if (i < B * H) { g_h0[i] = 0.f; g_c[i] = 0.f; }
}

// ---------------- double-buffered FFMA2 SGEMM + bias (gx GEMMs) ----------------
__global__ __launch_bounds__(256, 2) void sgemm_bias2(
    const float* __restrict__ A, const float* __restrict__ Bm,
    const float* __restrict__ bias, float* __restrict__ C,
    int M, int N, int K)
{
    __shared__ float As[2][8][128];
    __shared__ float Bs[2][8][128];
    int tid = threadIdx.x;
    int bx = blockIdx.x, by = blockIdx.y;
    int tx = tid & 15, ty = tid >> 4;

    const float* Ab = A + (size_t)by * 128 * K;
    const float* Bb = Bm + (size_t)bx * 128;

    int arow = tid >> 1, acol = (tid & 1) * 4;
    int brow = tid >> 5, bcol = (tid & 31) * 4;

    ull acc[8][4];
#pragma unroll
    for (int i = 0; i < 8; i++)
#pragma unroll
        for (int p = 0; p < 4; p++) acc[i][p] = 0ull;

    {
        float4 av = *(const float4*)(Ab + (size_t)arow * K + acol);
        float4 bv = *(const float4*)(Bb + (size_t)brow * N + bcol);
        As[0][acol + 0][arow] = av.x;
        As[0][acol + 1][arow] = av.y;
        As[0][acol + 2][arow] = av.z;
        As[0][acol + 3][arow] = av.w;
        *(float4*)&Bs[0][brow][bcol] = bv;
    }
    __syncthreads();

    int nk = K >> 3;
    for (int kt = 0; kt < nk; kt++) {
        int cur = kt & 1;
        float4 av, bv;
        bool more = (kt + 1 < nk);
        if (more) {
            av = *(const float4*)(Ab + (size_t)arow * K + (kt + 1) * 8 + acol);
            bv = *(const float4*)(Bb + (size_t)((kt + 1) * 8 + brow) * N + bcol);
        }
#pragma unroll
        for (int k = 0; k < 8; k++) {
            float ar[8];
            *(float4*)&ar[0] = *(const float4*)&As[cur][k][ty * 8];
            *(float4*)&ar[4] = *(const float4*)&As[cur][k][ty * 8 + 4];
            ull b2[4];
            const ull* bp = (const ull*)&Bs[cur][k][tx * 8];
            b2[0] = bp[0]; b2[1] = bp[1]; b2[2] = bp[2]; b2[3] = bp[3];
            ull a2[8];
#pragma unroll
            for (int i = 0; i < 8; i++) a2[i] = splat2(ar[i]);
#pragma unroll
            for (int i = 0; i < 8; i++)
#pragma unroll
                for (int p = 0; p < 4; p++)
                    acc[i][p] = fma2(a2[i], b2[p], acc[i][p]);
        }
        if (more) {
            int alt = cur ^ 1;
            As[alt][acol + 0][arow] = av.x;
            As[alt][acol + 1][arow] = av.y;
            As[alt][acol + 2][arow] = av.z;
            As[alt][acol + 3][arow] = av.w;
            *(float4*)&Bs[alt][brow][bcol] = bv;
        }
        __syncthreads();
    }

#pragma unroll
    for (int i = 0; i < 8; i++) {
        int row = by * 128 + ty * 8 + i;
        int col = bx * 128 + tx * 8;
        float* Cp = C + (size_t)row * N + col;
        const float* bp = bias + col;
        float c0, c1, c2, c3, c4, c5, c6, c7;
        unpack2(acc[i][0], c0, c1);
        unpack2(acc[i][1], c2, c3);
        unpack2(acc[i][2], c4, c5);
        unpack2(acc[i][3], c6, c7);
        float4 o0, o1;
        o0.x = c0 + bp[0]; o0.y = c1 + bp[1];
        o0.z = c2 + bp[2]; o0.w = c3 + bp[3];
        o1.x = c4 + bp[4]; o1.y = c5 + bp[5];
        o1.z = c6 + bp[6]; o1.w = c7 + bp[7];
        *(float4*)Cp = o0;
        *(float4*)(Cp + 4) = o1;
    }
}

// ---------------- fused LSTM timestep (exact R4 version) ----------------
#define WS_STRIDE (256 * 32)
#define HS_STRIDE (256 * 36)
#define LSTM_SMEM ((2 * WS_STRIDE + 2 * HS_STRIDE) * 4)

__global__ __launch_bounds__(256, 1) void lstm_step3(
    const float* __restrict__ gx, const float* __restrict__ Wh,
    const float* __restrict__ h_in, float* __restrict__ h_out,
    float* __restrict__ c_st, float* __restrict__ hseq, int t)
{
    extern __shared__ float sm[];
    float* ws = sm;
    float* hsb = sm + 2 * WS_STRIDE;
    float* red = sm;

    int tid = threadIdx.x;
    int s = tid >> 4;
    int tile = tid & 15;
    int bg = tile >> 2;
    int g = tile & 3;
    int j0 = blockIdx.x * 8;

    const float4* h4 = (const float4*)h_in;

#pragma unroll
    for (int l = 0; l < 8; l++) {
        int f = tid + l * 256;
        int k = f >> 3, wg = (f >> 1) & 3, half = f & 1;
        cp_async16(&ws[k * 32 + wg * 8 + half * 4],
                   Wh + (size_t)k * G + wg * H + j0 + half * 4);
    }
    cp_async_commit();
    {
        float4 hreg[8];
#pragma unroll
        for (int l = 0; l < 8; l++) {
            int q = tid + l * 256;
            hreg[l] = h4[(q >> 6) * 256 + (q & 63)];
        }
#pragma unroll
        for (int l = 0; l < 8; l++) {
            int q = tid + l * 256;
            int b = q >> 6, kl = (q & 63) * 4;
            hsb[(kl + 0) * 36 + b] = hreg[l].x;
            hsb[(kl + 1) * 36 + b] = hreg[l].y;
            hsb[(kl + 2) * 36 + b] = hreg[l].z;
            hsb[(kl + 3) * 36 + b] = hreg[l].w;
        }
    }
    cp_async_wait_all();
    __syncthreads();

    ull acc[8][4];
#pragma unroll
    for (int i = 0; i < 8; i++)
#pragma unroll
        for (int p = 0; p < 4; p++) acc[i][p] = 0ull;

    for (int c = 0; c < 4; c++) {
        int d = c & 1;
        float4 hreg[8];
        bool more = (c < 3);
        if (more) {
            float* wsn = ws + (d ^ 1) * WS_STRIDE;
#pragma unroll
            for (int l = 0; l < 8; l++) {
                int f = tid + l * 256;
                int k = f >> 3, wg = (f >> 1) & 3, half = f & 1;
                cp_async16(&wsn[k * 32 + wg * 8 + half * 4],
                           Wh + (size_t)(c * 256 + 256 + k) * G + wg * H + j0 + half * 4);
            }
            cp_async_commit();
#pragma unroll
            for (int l = 0; l < 8; l++) {
                int q = tid + l * 256;
                hreg[l] = h4[(q >> 6) * 256 + (c + 1) * 64 + (q & 63)];
            }
        }

        const float* wsc = ws + d * WS_STRIDE;
        const float* hsc = hsb + d * HS_STRIDE;
#pragma unroll 4
        for (int kk = 0; kk < 16; kk++) {
            int k = kk * 16 + s;
            float hv[8];
            *(float4*)&hv[0] = *(const float4*)&hsc[k * 36 + bg * 8];
            *(float4*)&hv[4] = *(const float4*)&hsc[k * 36 + bg * 8 + 4];
            ull w2[4];
            const ull* wp = (const ull*)&wsc[k * 32 + g * 8];
            w2[0] = wp[0]; w2[1] = wp[1]; w2[2] = wp[2]; w2[3] = wp[3];
            ull a2[8];
#pragma unroll
            for (int i = 0; i < 8; i++) a2[i] = splat2(hv[i]);
#pragma unroll
            for (int i = 0; i < 8; i++)
#pragma unroll
                for (int p = 0; p < 4; p++)
                    acc[i][p] = fma2(a2[i], w2[p], acc[i][p]);
        }

        if (more) {
            float* hsn = hsb + (d ^ 1) * HS_STRIDE;
#pragma unroll
            for (int l = 0; l < 8; l++) {
                int q = tid + l * 256;
                int b = q >> 6, kl = (q & 63) * 4;
                hsn[(kl + 0) * 36 + b] = hreg[l].x;
                hsn[(kl + 1) * 36 + b] = hreg[l].y;
                hsn[(kl + 2) * 36 + b] = hreg[l].z;
                hsn[(kl + 3) * 36 + b] = hreg[l].w;
            }
        }
        cp_async_wait_all();
        __syncthreads();
    }

    {
        int base = ((s * 4 + bg) * 4 + g) * 64;
#pragma unroll
        for (int i = 0; i < 8; i++)
#pragma unroll
            for (int p = 0; p < 4; p++) {
                float lo, hi;
                unpack2(acc[i][p], lo, hi);
                red[base + i * 8 + 2 * p] = lo;
                red[base + i * 8 + 2 * p + 1] = hi;
            }
    }
    __syncthreads();

    {
        int b = tid >> 3;
        int jj = tid & 7;
        float gate[4] = {0.f, 0.f, 0.f, 0.f};
        int bgi = b >> 3, ii = b & 7;
#pragma unroll
        for (int ss = 0; ss < 16; ss++) {
#pragma unroll
            for (int gg = 0; gg < 4; gg++)
                gate[gg] += red[((ss * 4 + bgi) * 4 + gg) * 64 + ii * 8 + jj];
        }
        int jg = j0 + jj;
        const float* gxr = gx + (size_t)(b * T + t) * G;
        float vi = gate[0] + gxr[0 * H + jg];
        float vj = gate[1] + gxr[1 * H + jg];
        float vf = gate[2] + gxr[2 * H + jg];
        float vo = gate[3] + gxr[3 * H + jg];
        float cold = c_st[b * H + jg];
        float si = 1.f / (1.f + expf(-vi));
        float sf = 1.f / (1.f + expf(-(vf + 1.f)));
        float so = 1.f / (1.f + expf(-vo));
        float cnew = sf * cold + si * tanhf(vj);
        float hnew = so * tanhf(cnew);
        c_st[b * H + jg] = cnew;
        h_out[b * H + jg] = hnew;
        hseq[(size_t)(b * T + t) * H + jg] = hnew;
    }
}

// ---------------- bf16 hi/lo converts ----------------
__global__ void convert_a_kernel(const float* __restrict__ src) {
    int row = blockIdx.x;
    int tid = threadIdx.x;
    float4 v = ((const float4*)(src + (size_t)row * H))[tid];
    int o = row * H + tid * 4;
    float f[4] = {v.x, v.y, v.z, v.w};
#pragma unroll
    for (int i = 0; i < 4; i++) {
        __nv_bfloat16 hi = __float2bfloat16(f[i]);
        __nv_bfloat16 lo = __float2bfloat16(f[i] - __bfloat162float(hi));
        g_ahi[o + i] = hi;
        g_alo[o + i] = lo;
    }
}

// transpose-convert Wd[k][n] (fp32) -> g_bhi/g_blo[n][k] (bf16)
__global__ __launch_bounds__(256) void convert_wd_kernel(const float* __restrict__ Wd) {
    __shared__ float tile[32][33];
    int tx = threadIdx.x & 31, ty = threadIdx.x >> 5;
    int n0 = blockIdx.x * 32, k0 = blockIdx.y * 32;
#pragma unroll
    for (int i = 0; i < 4; i++)
        tile[ty + 8 * i][tx] = Wd[(size_t)(k0 + ty + 8 * i) * V + n0 + tx];
    __syncthreads();
#pragma unroll
    for (int i = 0; i < 4; i++) {
        float v = tile[tx][ty + 8 * i];
        __nv_bfloat16 hi = __float2bfloat16(v);
        __nv_bfloat16 lo = __float2bfloat16(v - __bfloat162float(hi));
        size_t o = (size_t)(n0 + ty + 8 * i) * H + k0 + tx;
        g_bhi[o] = hi;
        g_blo[o] = lo;
    }
}

// ---------------- dense projection via mma.sync bf16 hi/lo 3-pass ----------------
// out[4096, 32000] = hseq1 @ Wd + bd
// Block tile 128x128, 8 warps (2m x 4n), warp tile 64x32, K chunks of 64 bf16.
// smem per stage: Ahi|Alo|Bhi|Blo, each 128 rows x 128B (swizzled) = 64KB; x2 stages.
#define DTILE 16384
#define DSTAGE (4 * DTILE)
#define DENSE_SMEM (2 * DSTAGE)

__device__ __forceinline__ void dense_load(unsigned sbase, int m0, int n0, int kc) {
    int tid = threadIdx.x;
#pragma unroll
    for (int i = 0; i < 16; i++) {
        int idx = tid + i * 256;
        int tl = idx >> 10;           // 0=Ahi 1=Alo 2=Bhi 3=Blo
        int j = idx & 1023;
        int r = j >> 3, c = j & 7;
        const __nv_bfloat16* gb = (tl == 0) ? g_ahi : (tl == 1) ? g_alo
                                 : (tl == 2) ? g_bhi : g_blo;
        int grow = ((tl < 2) ? m0 : n0) + r;
        const __nv_bfloat16* src = gb + (size_t)grow * H + kc * 64 + c * 8;
        unsigned dst = sbase + tl * DTILE + swz((unsigned)(r * 128 + c * 16));
        cp_async16_s(dst, src);
    }
}

__global__ __launch_bounds__(256, 1) void dense_hmma(
    const float* __restrict__ bd, float* __restrict__ out)
{
    extern __shared__ __align__(128) char dsm[];
    unsigned sb = (unsigned)__cvta_generic_to_shared(dsm);
    int tid = threadIdx.x;
    int wid = tid >> 5, lane = tid & 31;
    int m0 = blockIdx.x * 128, n0 = blockIdx.y * 128;
    int wm = (wid & 1) * 64;       // warp m offset in tile
    int wn = (wid >> 1) * 32;      // warp n offset in tile
    int lrow = lane & 15, lch = lane >> 4;

    float acc[4][4][4];            // [mi][nj][frag]
#pragma unroll
    for (int mi = 0; mi < 4; mi++)
#pragma unroll
        for (int nj = 0; nj < 4; nj++)
#pragma unroll
            for (int q = 0; q < 4; q++) acc[mi][nj][q] = 0.f;

    dense_load(sb, m0, n0, 0);
    cp_async_commit();

    for (int kc = 0; kc < 16; kc++) {
        int d = kc & 1;
        unsigned stage = sb + d * DSTAGE;
        cp_async_wait_all();
        __syncthreads();
        if (kc + 1 < 16) {
            dense_load(sb + (d ^ 1) * DSTAGE, m0, n0, kc + 1);
            cp_async_commit();
        }

        // 3 passes: (Ahi,Bhi), (Ahi,Blo), (Alo,Bhi)
#pragma unroll
        for (int p = 0; p < 3; p++) {
            unsigned Ab = stage + ((p == 2) ? DTILE : 0);
            unsigned Bb = stage + 2 * DTILE + ((p == 1) ? DTILE : 0);
#pragma unroll
            for (int ks = 0; ks < 4; ks++) {
                unsigned a[4][4];
#pragma unroll
                for (int mi = 0; mi < 4; mi++) {
                    unsigned addr = Ab + swz((unsigned)((wm + mi * 16 + lrow) * 128
                                                        + ks * 32 + lch * 16));
                    ldm4(a[mi], addr);
                }
                unsigned bq[2][4];
#pragma unroll
                for (int bi = 0; bi < 2; bi++) {
                    unsigned addr = Bb + swz((unsigned)((wn + bi * 16 + lrow) * 128
                                                        + ks * 32 + lch * 16));
                    ldm4(bq[bi], addr);
                }
#pragma unroll
                for (int mi = 0; mi < 4; mi++)
#pragma unroll
                    for (int bi = 0; bi < 2; bi++) {
                        mma_bf16(acc[mi][bi * 2 + 0], a[mi], bq[bi][0], bq[bi][2]);
                        mma_bf16(acc[mi][bi * 2 + 1], a[mi], bq[bi][1], bq[bi][3]);
                    }
            }
        }
        __syncthreads();
    }

    // epilogue: direct stores with bias
    int gid = lane >> 2, tig = lane & 3;
#pragma unroll
    for (int mi = 0; mi < 4; mi++) {
#pragma unroll
        for (int nj = 0; nj < 4; nj++) {
            int row = m0 + wm + mi * 16 + gid;
            int col = n0 + wn + nj * 8 + tig * 2;
            float b0 = bd[col], b1 = bd[col + 1];
            float2 o0, o1;
            o0.x = acc[mi][nj][0] + b0; o0.y = acc[mi][nj][1] + b1;
            o1.x = acc[mi][nj][2] + b0; o1.y = acc[mi][nj][3] + b1;
            *(float2*)(out + (size_t)row * V + col) = o0;
            *(float2*)(out + (size_t)(row + 8) * V + col) = o1;
        }
    }
}

// ---------------- launcher ----------------
extern "C" void kernel_launch(void* const* d_in, const int* in_sizes, int n_in,
                              void* d_out, int out_size)
{
    const int*   input_seq = (const int*)d_in[0];
    const float* emb = (const float*)d_in[1];
    const float* W0  = (const float*)d_in[2];
    const float* b0  = (const float*)d_in[3];
    const float* W1  = (const float*)d_in[4];
    const float* b1  = (const float*)d_in[5];
    const float* Wd  = (const float*)d_in[6];
    const float* bd  = (const float*)d_in[7];
    float* out = (float*)d_out;
    (void)in_sizes; (void)n_in; (void)out_size;

    float *xemb, *gx, *hs0, *hs1, *h0, *h1, *cbuf;
    cudaGetSymbolAddress((void**)&xemb, g_xemb);
    cudaGetSymbolAddress((void**)&gx,   g_gx);
    cudaGetSymbolAddress((void**)&hs0,  g_hseq0);
    cudaGetSymbolAddress((void**)&hs1,  g_hseq1);
    cudaGetSymbolAddress((void**)&h0,   g_h0);
    cudaGetSymbolAddress((void**)&h1,   g_h1);
    cudaGetSymbolAddress((void**)&cbuf, g_c);

    cudaFuncSetAttribute(lstm_step3, cudaFuncAttributeMaxDynamicSharedMemorySize, LSTM_SMEM);
    cudaFuncSetAttribute(dense_hmma, cudaFuncAttributeMaxDynamicSharedMemorySize, DENSE_SMEM);

    // Wd transpose + bf16 hi/lo split (independent; overlaps with LSTM work)
    convert_wd_kernel<<<dim3(V / 32, H / 32), 256>>>(Wd);

    // embedding
    embed_kernel<<<BT, 256>>>(input_seq, emb);

    // layer-0 input-path gates
    dim3 gGX(G / 128, BT / 128);
    sgemm_bias2<<<gGX, 256>>>(xemb, W0, b0, gx, BT, G, E);

    // layer-0 recurrence
    zero_state_kernel<<<(B * H + 255) / 256, 256>>>();
    for (int t = 0; t < T; t++) {
        float* hin  = (t & 1) ? h1 : h0;
        float* hout = (t & 1) ? h0 : h1;
        lstm_step3<<<128, 256, LSTM_SMEM>>>(gx, W0 + (size_t)E * G, hin, hout, cbuf, hs0, t);
    }

    // layer-1 input-path gates
    sgemm_bias2<<<gGX, 256>>>(hs0, W1, b1, gx, BT, G, H);

    // layer-1 recurrence
    zero_state_kernel<<<(B * H + 255) / 256, 256>>>();
    for (int t = 0; t < T; t++) {
        float* hin  = (t & 1) ? h1 : h0;
        float* hout = (t & 1) ? h0 : h1;
        lstm_step3<<<128, 256, LSTM_SMEM>>>(gx, W1 + (size_t)H * G, hin, hout, cbuf, hs1, t);
    }

    // hseq1 -> bf16 hi/lo
    convert_a_kernel<<<BT, 256>>>(hs1);

    // dense projection on tensor cores (mma.sync bf16, 3-pass hi/lo)
    dense_hmma<<<dim3(BT / 128, V / 128), 256, DENSE_SMEM>>>(bd, out);
}

// round 10
// speedup vs baseline: 3.7829x; 1.8032x over previous
#include <cuda_runtime.h>
#include <cuda_bf16.h>
#include <math.h>

#define B 32
#define T 128
#define BT 4096
#define E 1024
#define H 1024
#define G 4096
#define V 32000

typedef unsigned long long ull;

// ---------------- cp.async helpers ----------------
__device__ __forceinline__ void cp_async16_s(unsigned dst, const void* gptr) {
    asm volatile("cp.async.cg.shared.global [%0], [%1], 16;\n" :: "r"(dst), "l"(gptr));
}
__device__ __forceinline__ void cp_async_commit() {
    asm volatile("cp.async.commit_group;\n");
}
__device__ __forceinline__ void cp_async_wait_all() {
    asm volatile("cp.async.wait_group 0;\n" ::: "memory");
}

// ---------------- mma.sync / ldmatrix helpers ----------------
__device__ __forceinline__ void ldm4(unsigned* r, unsigned addr) {
    asm volatile("ldmatrix.sync.aligned.m8n8.x4.shared.b16 {%0,%1,%2,%3}, [%4];"
                 : "=r"(r[0]), "=r"(r[1]), "=r"(r[2]), "=r"(r[3]) : "r"(addr));
}
__device__ __forceinline__ void mma_bf16(float* c, const unsigned* a, unsigned b0, unsigned b1) {
    asm volatile(
        "mma.sync.aligned.m16n8k16.row.col.f32.bf16.bf16.f32 "
        "{%0,%1,%2,%3}, {%4,%5,%6,%7}, {%8,%9}, {%0,%1,%2,%3};"
        : "+f"(c[0]), "+f"(c[1]), "+f"(c[2]), "+f"(c[3])
        : "r"(a[0]), "r"(a[1]), "r"(a[2]), "r"(a[3]), "r"(b0), "r"(b1));
}
__device__ __forceinline__ unsigned swz(unsigned off) {
    return off ^ ((off >> 3) & 0x70);
}

// ---------------- device scratch ----------------
__device__ __align__(16) float g_xemb[BT * E];
__device__ __align__(16) float g_gx[BT * G];
__device__ __align__(16) float g_hseq0[BT * H];
__device__ __align__(16) float g_hseq1[BT * H];
__device__ __align__(16) float g_c[B * H];
// A operands (bf16 hi/lo), reused sequentially for xemb / hseq0 / hseq1
__device__ __align__(16) __nv_bfloat16 g_ahi[BT * H];
__device__ __align__(16) __nv_bfloat16 g_alo[BT * H];
// dense weights
__device__ __align__(16) __nv_bfloat16 g_bhi[(size_t)V * H];
__device__ __align__(16) __nv_bfloat16 g_blo[(size_t)V * H];
// x-path weights, transposed [n][k]
__device__ __align__(16) __nv_bfloat16 g_w0xhi[G * H];
__device__ __align__(16) __nv_bfloat16 g_w0xlo[G * H];
__device__ __align__(16) __nv_bfloat16 g_w1xhi[G * H];
__device__ __align__(16) __nv_bfloat16 g_w1xlo[G * H];
// recurrent weights, transposed + gate-block permuted [prow][k]
__device__ __align__(16) __nv_bfloat16 g_wh0hi[G * H];
__device__ __align__(16) __nv_bfloat16 g_wh0lo[G * H];
__device__ __align__(16) __nv_bfloat16 g_wh1hi[G * H];
__device__ __align__(16) __nv_bfloat16 g_wh1lo[G * H];
// h state as bf16 hi/lo, ping-pong
__device__ __align__(16) __nv_bfloat16 g_hbh0[B * H];
__device__ __align__(16) __nv_bfloat16 g_hbl0[B * H];
__device__ __align__(16) __nv_bfloat16 g_hbh1[B * H];
__device__ __align__(16) __nv_bfloat16 g_hbl1[B * H];

// ---------------- embedding gather ----------------
__global__ void embed_kernel(const int* __restrict__ idx, const float* __restrict__ emb) {
    int row = blockIdx.x;
    int tok = idx[row];
    const float4* src = (const float4*)(emb + (size_t)tok * E);
    float4* dst = (float4*)(g_xemb + (size_t)row * E);
    dst[threadIdx.x] = src[threadIdx.x];
}

// zero c and the t=0 h ping buffers
__global__ void zero_state_kernel() {
    int i = blockIdx.x * blockDim.x + threadIdx.x;
    if (i < B * H) {
        g_c[i] = 0.f;
        g_hbh0[i] = __float2bfloat16(0.f);
        g_hbl0[i] = __float2bfloat16(0.f);
    }
}

// ---------------- bf16 hi/lo converts ----------------
__global__ void convert_a_kernel(const float* __restrict__ src) {
    int row = blockIdx.x;
    int tid = threadIdx.x;
    float4 v = ((const float4*)(src + (size_t)row * H))[tid];
    int o = row * H + tid * 4;
    float f[4] = {v.x, v.y, v.z, v.w};
#pragma unroll
    for (int i = 0; i < 4; i++) {
        __nv_bfloat16 hi = __float2bfloat16(f[i]);
        __nv_bfloat16 lo = __float2bfloat16(f[i] - __bfloat162float(hi));
        g_ahi[o + i] = hi;
        g_alo[o + i] = lo;
    }
}

// transpose-convert src[k][N] fp32 -> dhi/dlo[n][1024] bf16 (K = 1024)
__global__ __launch_bounds__(256) void convert_wt(
    const float* __restrict__ src, __nv_bfloat16* __restrict__ dhi,
    __nv_bfloat16* __restrict__ dlo, int N)
{
    __shared__ float tile[32][33];
    int tx = threadIdx.x & 31, ty = threadIdx.x >> 5;
    int n0 = blockIdx.x * 32, k0 = blockIdx.y * 32;
#pragma unroll
    for (int i = 0; i < 4; i++)
        tile[ty + 8 * i][tx] = src[(size_t)(k0 + ty + 8 * i) * N + n0 + tx];
    __syncthreads();
#pragma unroll
    for (int i = 0; i < 4; i++) {
        float v = tile[tx][ty + 8 * i];
        __nv_bfloat16 hi = __float2bfloat16(v);
        __nv_bfloat16 lo = __float2bfloat16(v - __bfloat162float(hi));
        size_t o = (size_t)(n0 + ty + 8 * i) * H + k0 + tx;
        dhi[o] = hi;
        dlo[o] = lo;
    }
}

// same, with gate-block row permutation: n = g*1024 + j  ->  prow = (j/8)*32 + g*8 + (j%8)
__global__ __launch_bounds__(256) void convert_wt_perm(
    const float* __restrict__ src, __nv_bfloat16* __restrict__ dhi,
    __nv_bfloat16* __restrict__ dlo)
{
    __shared__ float tile[32][33];
    int tx = threadIdx.x & 31, ty = threadIdx.x >> 5;
    int n0 = blockIdx.x * 32, k0 = blockIdx.y * 32;
#pragma unroll
    for (int i = 0; i < 4; i++)
        tile[ty + 8 * i][tx] = src[(size_t)(k0 + ty + 8 * i) * G + n0 + tx];
    __syncthreads();
#pragma unroll
    for (int i = 0; i < 4; i++) {
        float v = tile[tx][ty + 8 * i];
        __nv_bfloat16 hi = __float2bfloat16(v);
        __nv_bfloat16 lo = __float2bfloat16(v - __bfloat162float(hi));
        int n = n0 + ty + 8 * i;
        int g = n >> 10, j = n & 1023;
        int prow = (j >> 3) * 32 + g * 8 + (j & 7);
        size_t o = (size_t)prow * H + k0 + tx;
        dhi[o] = hi;
        dlo[o] = lo;
    }
}

// ---------------- generic HMMA GEMM: C[M,N] = A @ B^T + bias ----------------
// A = (Ahi + Alo) [M][1024], B = (Bhi + Blo) [N][1024]; 3-pass hi/lo split.
// Block tile 128x128, 8 warps (2m x 4n), K chunks of 64.
#define DTILE 16384
#define DSTAGE (4 * DTILE)
#define DENSE_SMEM (2 * DSTAGE)

__device__ __forceinline__ void hmma_load(
    unsigned sbase, int m0, int n0, int kc,
    const __nv_bfloat16* Ahi, const __nv_bfloat16* Alo,
    const __nv_bfloat16* Bhi, const __nv_bfloat16* Blo)
{
    int tid = threadIdx.x;
#pragma unroll
    for (int i = 0; i < 16; i++) {
        int idx = tid + i * 256;
        int tl = idx >> 10;           // 0=Ahi 1=Alo 2=Bhi 3=Blo
        int j = idx & 1023;
        int r = j >> 3, c = j & 7;
        const __nv_bfloat16* gb = (tl == 0) ? Ahi : (tl == 1) ? Alo
                                 : (tl == 2) ? Bhi : Blo;
        int grow = ((tl < 2) ? m0 : n0) + r;
        const __nv_bfloat16* src = gb + (size_t)grow * H + kc * 64 + c * 8;
        unsigned dst = sbase + tl * DTILE + swz((unsigned)(r * 128 + c * 16));
        cp_async16_s(dst, src);
    }
}

__global__ __launch_bounds__(256, 1) void hmma_gemm(
    const __nv_bfloat16* __restrict__ Ahi, const __nv_bfloat16* __restrict__ Alo,
    const __nv_bfloat16* __restrict__ Bhi, const __nv_bfloat16* __restrict__ Blo,
    const float* __restrict__ bias, float* __restrict__ C, int N)
{
    extern __shared__ __align__(128) char dsm[];
    unsigned sb = (unsigned)__cvta_generic_to_shared(dsm);
    int tid = threadIdx.x;
    int wid = tid >> 5, lane = tid & 31;
    int m0 = blockIdx.x * 128, n0 = blockIdx.y * 128;
    int wm = (wid & 1) * 64;
    int wn = (wid >> 1) * 32;
    int lrow = lane & 15, lch = lane >> 4;

    float acc[4][4][4];
#pragma unroll
    for (int mi = 0; mi < 4; mi++)
#pragma unroll
        for (int nj = 0; nj < 4; nj++)
#pragma unroll
            for (int q = 0; q < 4; q++) acc[mi][nj][q] = 0.f;

    hmma_load(sb, m0, n0, 0, Ahi, Alo, Bhi, Blo);
    cp_async_commit();

    for (int kc = 0; kc < 16; kc++) {
        int d = kc & 1;
        unsigned stage = sb + d * DSTAGE;
        cp_async_wait_all();
        __syncthreads();
        if (kc + 1 < 16) {
            hmma_load(sb + (d ^ 1) * DSTAGE, m0, n0, kc + 1, Ahi, Alo, Bhi, Blo);
            cp_async_commit();
        }

#pragma unroll
        for (int p = 0; p < 3; p++) {
            unsigned Ab = stage + ((p == 2) ? DTILE : 0);
            unsigned Bb = stage + 2 * DTILE + ((p == 1) ? DTILE : 0);
#pragma unroll
            for (int ks = 0; ks < 4; ks++) {
                unsigned a[4][4];
#pragma unroll
                for (int mi = 0; mi < 4; mi++) {
                    unsigned addr = Ab + swz((unsigned)((wm + mi * 16 + lrow) * 128
                                                        + ks * 32 + lch * 16));
                    ldm4(a[mi], addr);
                }
                unsigned bq[2][4];
#pragma unroll
                for (int bi = 0; bi < 2; bi++) {
                    unsigned addr = Bb + swz((unsigned)((wn + bi * 16 + lrow) * 128
                                                        + ks * 32 + lch * 16));
                    ldm4(bq[bi], addr);
                }
#pragma unroll
                for (int mi = 0; mi < 4; mi++)
#pragma unroll
                    for (int bi = 0; bi < 2; bi++) {
                        mma_bf16(acc[mi][bi * 2 + 0], a[mi], bq[bi][0], bq[bi][2]);
                        mma_bf16(acc[mi][bi * 2 + 1], a[mi], bq[bi][1], bq[bi][3]);
                    }
            }
        }
        __syncthreads();
    }

    int gid = lane >> 2, tig = lane & 3;
#pragma unroll
    for (int mi = 0; mi < 4; mi++) {
#pragma unroll
        for (int nj = 0; nj < 4; nj++) {
            int row = m0 + wm + mi * 16 + gid;
            int col = n0 + wn + nj * 8 + tig * 2;
            float b0 = bias[col], b1 = bias[col + 1];
            float2 o0, o1;
            o0.x = acc[mi][nj][0] + b0; o0.y = acc[mi][nj][1] + b1;
            o1.x = acc[mi][nj][2] + b0; o1.y = acc[mi][nj][3] + b1;
            *(float2*)(C + (size_t)row * N + col) = o0;
            *(float2*)(C + (size_t)(row + 8) * N + col) = o1;
        }
    }
}

// ---------------- HMMA LSTM timestep ----------------
// 128 blocks; block bx owns hidden units j0 = bx*8 .. +7 (all 4 gates = 32
// permuted weight rows n0 = bx*32). Per K-chunk of 128: stage h(hi/lo) and
// Wh^T(hi/lo), warp w computes k-step w (3 hi/lo passes), split-K reduce over
// 8 warps in smem, fused cell update emits hseq fp32 + next-step h bf16 hi/lo.
// smem: 2 stages x 32KB (A 2x8KB + B 2x8KB, each as 2 sub-tiles of 32x64)
//       + red[8][32][32] fp32 (32KB) = 96KB
#define RSTAGE 32768
#define RRED 65536
#define R_SMEM 98304

__device__ __forceinline__ void lstm_stage_load(
    unsigned base, int kc,
    const __nv_bfloat16* hin_hi, const __nv_bfloat16* hin_lo,
    const __nv_bfloat16* whhi, const __nv_bfloat16* whlo, int n0)
{
    int tid = threadIdx.x;
#pragma unroll
    for (int i = 0; i < 8; i++) {
        int idx = tid + i * 256;
        int part = idx >> 9;          // 0=Ahi 1=Alo 2=Bhi 3=Blo
        int j = idx & 511;
        int sub = j >> 8, jj = j & 255;
        int r = jj >> 3, c8 = jj & 7;
        int koff = kc * 128 + sub * 64 + c8 * 8;
        const __nv_bfloat16* src;
        if (part == 0)      src = hin_hi + r * H + koff;
        else if (part == 1) src = hin_lo + r * H + koff;
        else if (part == 2) src = whhi + (size_t)(n0 + r) * H + koff;
        else                src = whlo + (size_t)(n0 + r) * H + koff;
        unsigned dst = base + part * 8192 + sub * 4096 + swz((unsigned)(r * 128 + c8 * 16));
        cp_async16_s(dst, src);
    }
}

__global__ __launch_bounds__(256, 1) void lstm_hmma(
    const float* __restrict__ gx,
    const __nv_bfloat16* __restrict__ whhi, const __nv_bfloat16* __restrict__ whlo,
    const __nv_bfloat16* __restrict__ hin_hi, const __nv_bfloat16* __restrict__ hin_lo,
    __nv_bfloat16* __restrict__ hout_hi, __nv_bfloat16* __restrict__ hout_lo,
    float* __restrict__ c_st, float* __restrict__ hseq, int t)
{
    extern __shared__ __align__(128) char rsm[];
    unsigned sb = (unsigned)__cvta_generic_to_shared(rsm);
    float* red = (float*)(rsm + RRED);
    int tid = threadIdx.x, wid = tid >> 5, lane = tid & 31;
    int n0 = blockIdx.x * 32;
    int j0 = blockIdx.x * 8;

    lstm_stage_load(sb, 0, hin_hi, hin_lo, whhi, whlo, n0);
    cp_async_commit();

    float acc[2][4][4];
#pragma unroll
    for (int mi = 0; mi < 2; mi++)
#pragma unroll
        for (int nj = 0; nj < 4; nj++)
#pragma unroll
            for (int q = 0; q < 4; q++) acc[mi][nj][q] = 0.f;

    int sub = wid >> 2, kk = wid & 3;
    int lrow = lane & 15, lch = lane >> 4;

    for (int c = 0; c < 8; c++) {
        int d = c & 1;
        unsigned stage = sb + d * RSTAGE;
        cp_async_wait_all();
        __syncthreads();
        if (c + 1 < 8) {
            lstm_stage_load(sb + (d ^ 1) * RSTAGE, c + 1, hin_hi, hin_lo, whhi, whlo, n0);
            cp_async_commit();
        }

        unsigned Ah = stage + sub * 4096;
        unsigned Al = stage + 8192 + sub * 4096;
        unsigned Bh = stage + 16384 + sub * 4096;
        unsigned Bl = stage + 24576 + sub * 4096;

        unsigned ahi[2][4], alo[2][4], bhi[2][4], blo[2][4];
#pragma unroll
        for (int mi = 0; mi < 2; mi++) {
            unsigned off = swz((unsigned)((mi * 16 + lrow) * 128 + kk * 32 + lch * 16));
            ldm4(ahi[mi], Ah + off);
            ldm4(alo[mi], Al + off);
            ldm4(bhi[mi], Bh + off);
            ldm4(blo[mi], Bl + off);
        }
#pragma unroll
        for (int mi = 0; mi < 2; mi++)
#pragma unroll
            for (int bi = 0; bi < 2; bi++) {
                mma_bf16(acc[mi][bi * 2 + 0], ahi[mi], bhi[bi][0], bhi[bi][2]);
                mma_bf16(acc[mi][bi * 2 + 1], ahi[mi], bhi[bi][1], bhi[bi][3]);
                mma_bf16(acc[mi][bi * 2 + 0], ahi[mi], blo[bi][0], blo[bi][2]);
                mma_bf16(acc[mi][bi * 2 + 1], ahi[mi], blo[bi][1], blo[bi][3]);
                mma_bf16(acc[mi][bi * 2 + 0], alo[mi], bhi[bi][0], bhi[bi][2]);
                mma_bf16(acc[mi][bi * 2 + 1], alo[mi], bhi[bi][1], bhi[bi][3]);
            }
        __syncthreads();
    }

    // split-K partials: red[w][m][n]
    int gid = lane >> 2, tig = lane & 3;
#pragma unroll
    for (int mi = 0; mi < 2; mi++)
#pragma unroll
        for (int nj = 0; nj < 4; nj++) {
            int m = mi * 16 + gid, n = nj * 8 + tig * 2;
            *(float2*)&red[wid * 1024 + m * 32 + n] =
                make_float2(acc[mi][nj][0], acc[mi][nj][1]);
            *(float2*)&red[wid * 1024 + (m + 8) * 32 + n] =
                make_float2(acc[mi][nj][2], acc[mi][nj][3]);
        }
    __syncthreads();

    // fused cell update: thread -> (batch b, hidden jj)
    {
        int b = tid >> 3, jj = tid & 7;
        float gate[4] = {0.f, 0.f, 0.f, 0.f};
#pragma unroll
        for (int w = 0; w < 8; w++)
#pragma unroll
            for (int g = 0; g < 4; g++)
                gate[g] += red[w * 1024 + b * 32 + g * 8 + jj];
        int jg = j0 + jj;
        const float* gxr = gx + (size_t)(b * T + t) * G;
        float vi = gate[0] + gxr[0 * H + jg];
        float vj = gate[1] + gxr[1 * H + jg];
        float vf = gate[2] + gxr[2 * H + jg];
        float vo = gate[3] + gxr[3 * H + jg];
        float cold = c_st[b * H + jg];
        float si = 1.f / (1.f + expf(-vi));
        float sf = 1.f / (1.f + expf(-(vf + 1.f)));
        float so = 1.f / (1.f + expf(-vo));
        float cnew = sf * cold + si * tanhf(vj);
        float hnew = so * tanhf(cnew);
        c_st[b * H + jg] = cnew;
        hseq[(size_t)(b * T + t) * H + jg] = hnew;
        __nv_bfloat16 hi = __float2bfloat16(hnew);
        __nv_bfloat16 lo = __float2bfloat16(hnew - __bfloat162float(hi));
        hout_hi[b * H + jg] = hi;
        hout_lo[b * H + jg] = lo;
    }
}

// ---------------- launcher ----------------
extern "C" void kernel_launch(void* const* d_in, const int* in_sizes, int n_in,
                              void* d_out, int out_size)
{
    const int*   input_seq = (const int*)d_in[0];
    const float* emb = (const float*)d_in[1];
    const float* W0  = (const float*)d_in[2];
    const float* b0  = (const float*)d_in[3];
    const float* W1  = (const float*)d_in[4];
    const float* b1  = (const float*)d_in[5];
    const float* Wd  = (const float*)d_in[6];
    const float* bd  = (const float*)d_in[7];
    float* out = (float*)d_out;
    (void)in_sizes; (void)n_in; (void)out_size;

    float *xemb, *gx, *hs0, *hs1, *cbuf;
    __nv_bfloat16 *ahi, *alo, *bhi, *blo;
    __nv_bfloat16 *w0xhi, *w0xlo, *w1xhi, *w1xlo;
    __nv_bfloat16 *wh0hi, *wh0lo, *wh1hi, *wh1lo;
    __nv_bfloat16 *hbh0, *hbl0, *hbh1, *hbl1;
    cudaGetSymbolAddress((void**)&xemb, g_xemb);
    cudaGetSymbolAddress((void**)&gx,   g_gx);
    cudaGetSymbolAddress((void**)&hs0,  g_hseq0);
    cudaGetSymbolAddress((void**)&hs1,  g_hseq1);
    cudaGetSymbolAddress((void**)&cbuf, g_c);
    cudaGetSymbolAddress((void**)&ahi,  g_ahi);
    cudaGetSymbolAddress((void**)&alo,  g_alo);
    cudaGetSymbolAddress((void**)&bhi,  g_bhi);
    cudaGetSymbolAddress((void**)&blo,  g_blo);
    cudaGetSymbolAddress((void**)&w0xhi, g_w0xhi);
    cudaGetSymbolAddress((void**)&w0xlo, g_w0xlo);
    cudaGetSymbolAddress((void**)&w1xhi, g_w1xhi);
    cudaGetSymbolAddress((void**)&w1xlo, g_w1xlo);
    cudaGetSymbolAddress((void**)&wh0hi, g_wh0hi);
    cudaGetSymbolAddress((void**)&wh0lo, g_wh0lo);
    cudaGetSymbolAddress((void**)&wh1hi, g_wh1hi);
    cudaGetSymbolAddress((void**)&wh1lo, g_wh1lo);
    cudaGetSymbolAddress((void**)&hbh0, g_hbh0);
    cudaGetSymbolAddress((void**)&hbl0, g_hbl0);
    cudaGetSymbolAddress((void**)&hbh1, g_hbh1);
    cudaGetSymbolAddress((void**)&hbl1, g_hbl1);

    cudaFuncSetAttribute(hmma_gemm, cudaFuncAttributeMaxDynamicSharedMemorySize, DENSE_SMEM);
    cudaFuncSetAttribute(lstm_hmma, cudaFuncAttributeMaxDynamicSharedMemorySize, R_SMEM);

    // ---- weight converts (once, independent) ----
    convert_wt<<<dim3(G / 32, H / 32), 256>>>(W0, w0xhi, w0xlo, G);               // x-rows of W0
    convert_wt_perm<<<dim3(G / 32, H / 32), 256>>>(W0 + (size_t)E * G, wh0hi, wh0lo);
    convert_wt<<<dim3(G / 32, H / 32), 256>>>(W1, w1xhi, w1xlo, G);
    convert_wt_perm<<<dim3(G / 32, H / 32), 256>>>(W1 + (size_t)H * G, wh1hi, wh1lo);
    convert_wt<<<dim3(V / 32, H / 32), 256>>>(Wd, bhi, blo, V);

    // ---- embedding + layer-0 input gates ----
    embed_kernel<<<BT, 256>>>(input_seq, emb);
    convert_a_kernel<<<BT, 256>>>(xemb);
    hmma_gemm<<<dim3(BT / 128, G / 128), 256, DENSE_SMEM>>>(ahi, alo, w0xhi, w0xlo, b0, gx, G);

    // ---- layer-0 recurrence ----
    zero_state_kernel<<<(B * H + 255) / 256, 256>>>();
    for (int t = 0; t < T; t++) {
        const __nv_bfloat16* ihi = (t & 1) ? hbh1 : hbh0;
        const __nv_bfloat16* ilo = (t & 1) ? hbl1 : hbl0;
        __nv_bfloat16* ohi = (t & 1) ? hbh0 : hbh1;
        __nv_bfloat16* olo = (t & 1) ? hbl0 : hbl1;
        lstm_hmma<<<128, 256, R_SMEM>>>(gx, wh0hi, wh0lo, ihi, ilo, ohi, olo, cbuf, hs0, t);
    }

    // ---- layer-1 input gates ----
    convert_a_kernel<<<BT, 256>>>(hs0);
    hmma_gemm<<<dim3(BT / 128, G / 128), 256, DENSE_SMEM>>>(ahi, alo, w1xhi, w1xlo, b1, gx, G);

    // ---- layer-1 recurrence ----
    zero_state_kernel<<<(B * H + 255) / 256, 256>>>();
    for (int t = 0; t < T; t++) {
        const __nv_bfloat16* ihi = (t & 1) ? hbh1 : hbh0;
        const __nv_bfloat16* ilo = (t & 1) ? hbl1 : hbl0;
        __nv_bfloat16* ohi = (t & 1) ? hbh0 : hbh1;
        __nv_bfloat16* olo = (t & 1) ? hbl0 : hbl1;
        lstm_hmma<<<128, 256, R_SMEM>>>(gx, wh1hi, wh1lo, ihi, ilo, ohi, olo, cbuf, hs1, t);
    }

    // ---- dense projection ----
    convert_a_kernel<<<BT, 256>>>(hs1);
    hmma_gemm<<<dim3(BT / 128, V / 128), 256, DENSE_SMEM>>>(ahi, alo, bhi, blo, bd, out, V);
}